// round 15
// baseline (speedup 1.0000x reference)
#include <cuda_runtime.h>
#include <cstdint>

// FWHT over contiguous groups of 128 fp32 elements.
// READ-PATH EXPERIMENT: input fetched via cp.async.bulk (TMA bulk copy) —
// one 16 KB contiguous transfer per CTA into smem instead of 512 scattered
// 32 B LDG sectors — to test whether DRAM read-burst locality lifts the
// ~6.3 TB/s mixed-stream ceiling. Compute identical to the converged kernel:
// 16 contiguous floats/thread, stages h=1,2,4,8 intra-thread, h=16,32,64 via
// shfl.xor deltas 1,2,4. Stores remain direct STG.256 evict-first.

#define TILE_FLOATS 4096u   // per CTA: 256 threads * 16 floats = 16 KB

__device__ __forceinline__ uint32_t smem_u32(const void* p) {
    uint32_t a;
    asm("{ .reg .u64 t; cvta.to.shared.u64 t, %1; cvt.u32.u64 %0, t; }"
        : "=r"(a) : "l"(p));
    return a;
}

__device__ __forceinline__ void stg256_stream(float* p, const float* r) {
    asm volatile(
        "st.global.cs.v8.f32 [%0], {%1,%2,%3,%4,%5,%6,%7,%8};"
        :: "l"(p),
           "f"(r[0]), "f"(r[1]), "f"(r[2]), "f"(r[3]),
           "f"(r[4]), "f"(r[5]), "f"(r[6]), "f"(r[7])
        : "memory");
}

__global__ void __launch_bounds__(256) fwht128_kernel(
    const float* __restrict__ in, float* __restrict__ out)
{
    __shared__ alignas(128) float tile[TILE_FLOATS];
    __shared__ alignas(8) unsigned long long mbar;

    const unsigned int tid  = threadIdx.x;
    const unsigned int lane = tid & 31u;
    const unsigned int gbase = blockIdx.x * TILE_FLOATS;

    const uint32_t s_tile = smem_u32(tile);
    const uint32_t s_mbar = smem_u32(&mbar);

    if (tid == 0) {
        asm volatile("mbarrier.init.shared.b64 [%0], 1;" :: "r"(s_mbar) : "memory");
    }
    __syncthreads();

    if (tid == 0) {
        asm volatile("mbarrier.arrive.expect_tx.shared.b64 _, [%0], %1;"
                     :: "r"(s_mbar), "r"(TILE_FLOATS * 4u) : "memory");
        asm volatile(
            "cp.async.bulk.shared::cta.global.mbarrier::complete_tx::bytes "
            "[%0], [%1], %2, [%3];"
            :: "r"(s_tile), "l"(in + gbase), "r"(TILE_FLOATS * 4u), "r"(s_mbar)
            : "memory");
    }

    // Wait for the bulk load (parity 0; barrier used once per launch).
    {
        uint32_t done;
        asm volatile(
            "{\n\t.reg .pred p;\n\t"
            "mbarrier.try_wait.parity.acquire.cta.shared::cta.b64 p, [%1], 0;\n\t"
            "selp.b32 %0, 1, 0, p;\n\t}"
            : "=r"(done) : "r"(s_mbar) : "memory");
        if (!done) {
            asm volatile(
                "{\n\t.reg .pred P1;\n\t"
                "W_%=:\n\t"
                "mbarrier.try_wait.parity.acquire.cta.shared::cta.b64 P1, [%0], 0, 0x989680;\n\t"
                "@P1 bra.uni D_%=;\n\t"
                "bra.uni W_%=;\n\t"
                "D_%=:\n\t}"
                :: "r"(s_mbar) : "memory");
        }
    }

    // Each thread: 16 contiguous floats from smem (4x LDS.128).
    float e[16];
    {
        const float4* tp = reinterpret_cast<const float4*>(tile + tid * 16u);
        #pragma unroll
        for (int q = 0; q < 4; ++q) {
            float4 v = tp[q];
            e[q * 4 + 0] = v.x; e[q * 4 + 1] = v.y;
            e[q * 4 + 2] = v.z; e[q * 4 + 3] = v.w;
        }
    }

    // Intra-thread stages h=1,2,4,8 (FWHT-16 on contiguous elements).
    float t;
    #pragma unroll
    for (int h = 1; h <= 8; h <<= 1) {
        #pragma unroll
        for (int i = 0; i < 16; ++i) {
            if ((i & h) == 0) {
                t = e[i];
                e[i]     = t + e[i + h];
                e[i + h] = t - e[i + h];
            }
        }
    }

    // Cross-lane stages h=16,32,64 -> shfl.xor deltas 1,2,4 (within 8 lanes).
    #pragma unroll
    for (int d = 1; d <= 4; d <<= 1) {
        bool up = (lane & (unsigned)d) != 0u;
        #pragma unroll
        for (int k = 0; k < 16; ++k) {
            float q = __shfl_xor_sync(0xffffffffu, e[k], d);
            e[k] = up ? (q - e[k]) : (e[k] + q);
        }
    }

    const float S = 0.08838834764831845f;  // 1/sqrt(128)
    const unsigned int obase = gbase + tid * 16u;
    float r[8];
    #pragma unroll
    for (int k = 0; k < 8; ++k) r[k] = e[k] * S;
    stg256_stream(out + obase, r);
    #pragma unroll
    for (int k = 0; k < 8; ++k) r[k] = e[k + 8] * S;
    stg256_stream(out + obase + 8u, r);
}

extern "C" void kernel_launch(void* const* d_in, const int* in_sizes, int n_in,
                              void* d_out, int out_size)
{
    const float* x = (const float*)d_in[0];
    float* y = (float*)d_out;
    unsigned int n = (unsigned int)in_sizes[0];   // 67108864
    unsigned int grid = n / TILE_FLOATS;          // = 16384, exact
    fwht128_kernel<<<grid, 256>>>(x, y);
}

// round 16
// speedup vs baseline: 1.0844x; 1.0844x over previous
#include <cuda_runtime.h>
#include <cstdint>

// FWHT over contiguous groups of 128 fp32 elements — FINAL CONVERGED KERNEL.
// Best measured: 81.89 us; reproduced at 81.95-81.98 across four benches.
//
// Layout: 8 lanes per group; each thread holds 16 CONTIGUOUS elements
// (2x 256-bit LDG). Stages h=1,2,4,8 are intra-thread register butterflies;
// stages h=16,32,64 are shfl.xor with deltas 1,2,4 (3 shuffles/element).
// 32 regs, no smem, no barriers, exact-cover grid (16384 x 256).
//
// Roofline verdict (15 rounds, 14 configs): pinned at the sustained 1:1
// read:write HBM3e ceiling, ~6.3-6.4 TB/s (~80% of 8 TB/s spec), with
// traffic at the 512 MB/replay algorithmic minimum. Falsified levers:
// MLP (1-8), occupancy (51-92%), shuffle count (5/4/3 per elem), access
// width (128/256-bit), persistence + software pipelining (regressed),
// L2 evict_last full & partitioned (no cross-replay retention), block size,
// per-thread burst length, and the TMA bulk read path (regressed —
// LTS/DRAM ceiling is request-granularity-independent, as documented).

__device__ __forceinline__ void ldg256_keep(const float* p, float* r) {
    asm volatile(
        "ld.global.nc.L2::evict_last.v8.f32 {%0,%1,%2,%3,%4,%5,%6,%7}, [%8];"
        : "=f"(r[0]), "=f"(r[1]), "=f"(r[2]), "=f"(r[3]),
          "=f"(r[4]), "=f"(r[5]), "=f"(r[6]), "=f"(r[7])
        : "l"(p));
}

__device__ __forceinline__ void stg256_stream(float* p, const float* r) {
    asm volatile(
        "st.global.cs.v8.f32 [%0], {%1,%2,%3,%4,%5,%6,%7,%8};"
        :: "l"(p),
           "f"(r[0]), "f"(r[1]), "f"(r[2]), "f"(r[3]),
           "f"(r[4]), "f"(r[5]), "f"(r[6]), "f"(r[7])
        : "memory");
}

__global__ void __launch_bounds__(256) fwht128_kernel(
    const float* __restrict__ in, float* __restrict__ out)
{
    const unsigned int lane = threadIdx.x & 31u;
    // Each thread: 16 contiguous floats. Each warp: 512 floats = 4 groups.
    const unsigned int base = (blockIdx.x * 256u + threadIdx.x) * 16u;

    float e[16];
    ldg256_keep(in + base, e);
    ldg256_keep(in + base + 8u, e + 8);

    // Intra-thread stages h=1,2,4,8 (FWHT-16 on contiguous elements).
    float t;
    #pragma unroll
    for (int h = 1; h <= 8; h <<= 1) {
        #pragma unroll
        for (int i = 0; i < 16; ++i) {
            if ((i & h) == 0) {
                t = e[i];
                e[i]     = t + e[i + h];
                e[i + h] = t - e[i + h];
            }
        }
    }

    // Cross-lane stages h=16,32,64 -> shfl.xor deltas 1,2,4 (within 8 lanes).
    #pragma unroll
    for (int d = 1; d <= 4; d <<= 1) {
        bool up = (lane & (unsigned)d) != 0u;
        #pragma unroll
        for (int k = 0; k < 16; ++k) {
            float q = __shfl_xor_sync(0xffffffffu, e[k], d);
            e[k] = up ? (q - e[k]) : (e[k] + q);
        }
    }

    const float S = 0.08838834764831845f;  // 1/sqrt(128)
    float r[8];
    #pragma unroll
    for (int k = 0; k < 8; ++k) r[k] = e[k] * S;
    stg256_stream(out + base, r);
    #pragma unroll
    for (int k = 0; k < 8; ++k) r[k] = e[k + 8] * S;
    stg256_stream(out + base + 8u, r);
}

extern "C" void kernel_launch(void* const* d_in, const int* in_sizes, int n_in,
                              void* d_out, int out_size)
{
    const float* x = (const float*)d_in[0];
    float* y = (float*)d_out;
    unsigned int n = (unsigned int)in_sizes[0];   // 67108864
    unsigned int grid = n / (256u * 16u);         // = 16384, exact
    fwht128_kernel<<<grid, 256>>>(x, y);
}